// round 10
// baseline (speedup 1.0000x reference)
#include <cuda_runtime.h>

// 15x15 separable Gaussian, 8192x8192 f32, reflect pad, stride 1.
// Fused separable conv (R5 base + run=16 horizontal pass):
//   phase 1: vertical, packed f32x2 symmetric taps, register sliding window,
//            global -> smem vbuf
//   phase 2: horizontal, 16-output runs (8x LDS.128 per run, -33% LDS bytes),
//            scalar FFMA-imm, 4-row interleaved task map -> conflict-free
//            LDS.128 quarter-phases (VSTRIDE=132: row stride == 16 mod 128,
//            run stride == 64 mod 128; 8 lanes cover {0,16,...,112} mod 128)
// Coefficients hardcoded (problem-fixed Gaussian sigma=3, 15 taps);
// rel_err ~2.4e-7 verified across rounds.

#define IMW 8192
#define IMH 8192
#define TX  112          // output tile width (128 vbuf cols incl. 8+8 halo)
#define TY  80           // output tile height
#define VSTRIDE 132      // floats; 132*4=528 B, 528 % 128 == 16
#define NSX 74           // ceil(8192/112)
#define NSY 103          // ceil(8192/80)

static __device__ __forceinline__ int refl(int i) {
    i = (i < 0) ? -i : i;
    return (i >= IMW) ? (2 * IMW - 2 - i) : i;
}

__device__ __forceinline__ float2 ffma2(float2 a, float2 b, float2 c) {
    unsigned long long ua = *reinterpret_cast<unsigned long long*>(&a);
    unsigned long long ub = *reinterpret_cast<unsigned long long*>(&b);
    unsigned long long uc = *reinterpret_cast<unsigned long long*>(&c);
    unsigned long long ud;
    asm("fma.rn.f32x2 %0, %1, %2, %3;" : "=l"(ud) : "l"(ua), "l"(ub), "l"(uc));
    return *reinterpret_cast<float2*>(&ud);
}

__device__ __forceinline__ float2 fmul2(float2 a, float2 b) {
    unsigned long long ua = *reinterpret_cast<unsigned long long*>(&a);
    unsigned long long ub = *reinterpret_cast<unsigned long long*>(&b);
    unsigned long long ud;
    asm("mul.rn.f32x2 %0, %1, %2;" : "=l"(ud) : "l"(ua), "l"(ub));
    return *reinterpret_cast<float2*>(&ud);
}

__device__ __forceinline__ float2 fadd2(float2 a, float2 b) {
    unsigned long long ua = *reinterpret_cast<unsigned long long*>(&a);
    unsigned long long ub = *reinterpret_cast<unsigned long long*>(&b);
    unsigned long long ud;
    asm("add.rn.f32x2 %0, %1, %2;" : "=l"(ud) : "l"(ua), "l"(ub));
    return *reinterpret_cast<float2*>(&ud);
}

__global__ __launch_bounds__(256, 3)
void gauss_sep_kernel(const float* __restrict__ img,
                      float* __restrict__ out) {
    // normalized 1-D Gaussian, sigma=3, 15 taps (fp32)
    const float KC[15] = {
        0.00884695f, 0.01821590f, 0.03356240f, 0.05533503f,
        0.08163801f, 0.10777792f, 0.12732457f, 0.13459834f,
        0.12732457f, 0.10777792f, 0.08163801f, 0.05533503f,
        0.03356240f, 0.01821590f, 0.00884695f };

    __shared__ __align__(16) float vbuf[TY * VSTRIDE];   // 42.24 KB

    const int tid = threadIdx.x;
    const int bx = blockIdx.x;
    const int by = blockIdx.y;

    // ---- phase 1: vertical conv (packed f32x2, symmetric), global -> vbuf ----
    {
        const int pc = tid & 63;        // float2 column 0..63 (128 vbuf cols)
        const int g  = tid >> 6;        // y-group 0..3 (20 vbuf rows each)
        const int gxp = bx * TX - 8 + 2 * pc;          // global col of pair
        const bool xok = (gxp >= 0) && (gxp + 1 < IMW);
        const int rx0 = refl(gxp);
        const int rx1 = refl(gxp + 1);
        const int gy0 = by * TY + 20 * g;              // first output row of group

        float2 kyv[8];
        #pragma unroll
        for (int i = 0; i < 8; i++) kyv[i] = make_float2(KC[i], KC[i]);

        float2 win[15];
        #pragma unroll
        for (int i = 0; i < 14; i++) {
            const int ry = refl(gy0 - 7 + i);
            const float* rp = img + ry * IMW;
            if (xok) {
                win[i] = *reinterpret_cast<const float2*>(rp + gxp);
            } else {
                win[i].x = rp[rx0]; win[i].y = rp[rx1];
            }
        }
        #pragma unroll
        for (int s = 0; s < 20; s++) {
            const int ry = refl(gy0 + s + 7);
            const float* rp = img + ry * IMW;
            float2 nv;
            if (xok) {
                nv = *reinterpret_cast<const float2*>(rp + gxp);
            } else {
                nv.x = rp[rx0]; nv.y = rp[rx1];
            }
            win[(14 + s) % 15] = nv;

            float2 acc = fmul2(kyv[7], win[(s + 7) % 15]);
            #pragma unroll
            for (int i = 0; i < 7; i++)
                acc = ffma2(kyv[i],
                            fadd2(win[(s + i) % 15], win[(s + 14 - i) % 15]),
                            acc);

            *reinterpret_cast<float2*>(&vbuf[(20 * g + s) * VSTRIDE + 2 * pc]) = acc;
        }
    }
    __syncthreads();

    // ---- phase 2: horizontal conv, 16-output runs, FFMA-imm, vbuf -> out ----
    // 7 runs/row * 80 rows = 560 tasks. 4-row interleave: 8 consecutive lanes
    // hit smem addresses {0,16,...,112} mod 128 -> conflict-free LDS.128.
    {
        const int X0  = bx * TX;
        const int gyb = by * TY;

        for (int t = tid; t < 560; t += 256) {
            const int c   = t / 28;              // 0..19 (4-row block)
            const int u   = t - c * 28;
            const int row = 4 * c + (u & 3);     // 0..79
            const int q   = u >> 2;              // run 0..6

            const float* vp = &vbuf[row * VSTRIDE + q * 16];
            float w[32];
            #pragma unroll
            for (int j = 0; j < 8; j++) {
                const float4 f = *reinterpret_cast<const float4*>(vp + 4 * j);
                w[4 * j]     = f.x;
                w[4 * j + 1] = f.y;
                w[4 * j + 2] = f.z;
                w[4 * j + 3] = f.w;
            }

            // output k (0..15) at tile col q*16+k uses w[1+k .. 15+k]
            float o[16];
            #pragma unroll
            for (int k = 0; k < 16; k++) o[k] = KC[0] * w[1 + k];
            #pragma unroll
            for (int i = 1; i < 15; i++) {
                #pragma unroll
                for (int k = 0; k < 16; k++)
                    o[k] = fmaf(KC[i], w[1 + k + i], o[k]);
            }

            const int gy = gyb + row;
            const int gx = X0 + 16 * q;
            if (gy < IMH) {
                float* op = out + gy * IMW + gx;
                #pragma unroll
                for (int j = 0; j < 4; j++) {
                    if (gx + 4 * j + 3 < IMW) {
                        *reinterpret_cast<float4*>(op + 4 * j) =
                            make_float4(o[4 * j], o[4 * j + 1],
                                        o[4 * j + 2], o[4 * j + 3]);
                    }
                }
            }
        }
    }
}

extern "C" void kernel_launch(void* const* d_in, const int* in_sizes, int n_in,
                              void* d_out, int out_size) {
    const float* img = (const float*)d_in[0];
    float* out = (float*)d_out;

    dim3 grid(NSX, NSY);
    gauss_sep_kernel<<<grid, 256>>>(img, out);
}

// round 11
// speedup vs baseline: 1.0265x; 1.0265x over previous
#include <cuda_runtime.h>

// 15x15 separable Gaussian, 8192x8192 f32, reflect pad, stride 1.
// Fused separable conv (R5 structure, TY=128 + interior fast path):
//   phase 1: vertical, packed f32x2 symmetric taps, register sliding window,
//            global -> smem vbuf. Interior CTAs use a strided row pointer
//            (no refl, no per-row IMAD); border CTAs use the refl path.
//   phase 2: horizontal, 8-output runs, FFMA-imm, row-pair interleaved task
//            map for conflict-free LDS.128. 1792 tasks = exactly 7 per thread.
// Coefficients hardcoded (problem-fixed Gaussian sigma=3, 15 taps);
// rel_err ~2.4e-7 verified across rounds.

#define IMW 8192
#define IMH 8192
#define TX  112          // output tile width (128 vbuf cols incl. 8+8 halo)
#define TY  128          // output tile height (4 groups x 32 rows)
#define VSTRIDE 132      // floats; 132*4=528 B, 528 % 128 == 16
#define NSX 74           // ceil(8192/112)
#define NSY 64           // 8192/128 exact
#define SMEM_BYTES (TY * VSTRIDE * 4)   // 67584

static __device__ __forceinline__ int refl(int i) {
    i = (i < 0) ? -i : i;
    return (i >= IMW) ? (2 * IMW - 2 - i) : i;
}

__device__ __forceinline__ float2 ffma2(float2 a, float2 b, float2 c) {
    unsigned long long ua = *reinterpret_cast<unsigned long long*>(&a);
    unsigned long long ub = *reinterpret_cast<unsigned long long*>(&b);
    unsigned long long uc = *reinterpret_cast<unsigned long long*>(&c);
    unsigned long long ud;
    asm("fma.rn.f32x2 %0, %1, %2, %3;" : "=l"(ud) : "l"(ua), "l"(ub), "l"(uc));
    return *reinterpret_cast<float2*>(&ud);
}

__device__ __forceinline__ float2 fmul2(float2 a, float2 b) {
    unsigned long long ua = *reinterpret_cast<unsigned long long*>(&a);
    unsigned long long ub = *reinterpret_cast<unsigned long long*>(&b);
    unsigned long long ud;
    asm("mul.rn.f32x2 %0, %1, %2;" : "=l"(ud) : "l"(ua), "l"(ub));
    return *reinterpret_cast<float2*>(&ud);
}

__device__ __forceinline__ float2 fadd2(float2 a, float2 b) {
    unsigned long long ua = *reinterpret_cast<unsigned long long*>(&a);
    unsigned long long ub = *reinterpret_cast<unsigned long long*>(&b);
    unsigned long long ud;
    asm("add.rn.f32x2 %0, %1, %2;" : "=l"(ud) : "l"(ua), "l"(ub));
    return *reinterpret_cast<float2*>(&ud);
}

__global__ __launch_bounds__(256, 3)
void gauss_sep_kernel(const float* __restrict__ img,
                      float* __restrict__ out) {
    // normalized 1-D Gaussian, sigma=3, 15 taps (fp32)
    const float KC[15] = {
        0.00884695f, 0.01821590f, 0.03356240f, 0.05533503f,
        0.08163801f, 0.10777792f, 0.12732457f, 0.13459834f,
        0.12732457f, 0.10777792f, 0.08163801f, 0.05533503f,
        0.03356240f, 0.01821590f, 0.00884695f };

    extern __shared__ __align__(16) float vbuf[];   // TY * VSTRIDE floats

    const int tid = threadIdx.x;
    const int bx = blockIdx.x;
    const int by = blockIdx.y;

    // ---- phase 1: vertical conv (packed f32x2, symmetric), global -> vbuf ----
    {
        const int pc = tid & 63;        // float2 column 0..63 (128 vbuf cols)
        const int g  = tid >> 6;        // y-group 0..3 (32 vbuf rows each)
        const int gxp = bx * TX - 8 + 2 * pc;          // global col of pair
        const int gy0 = by * TY + 32 * g;              // first output row of group

        float2 kyv[8];
        #pragma unroll
        for (int i = 0; i < 8; i++) kyv[i] = make_float2(KC[i], KC[i]);

        float2 win[15];

        const bool interior = (bx > 0) && (bx < NSX - 1) && (by > 0) && (by < NSY - 1);

        if (interior) {
            // fast path: no reflection anywhere; strided row pointer
            const float* rp = img + (size_t)(gy0 - 7) * IMW + gxp;
            #pragma unroll
            for (int i = 0; i < 14; i++) {
                win[i] = *reinterpret_cast<const float2*>(rp);
                rp += IMW;
            }
            #pragma unroll
            for (int s = 0; s < 32; s++) {
                const float2 nv = *reinterpret_cast<const float2*>(rp);
                rp += IMW;
                win[(14 + s) % 15] = nv;

                float2 acc = fmul2(kyv[7], win[(s + 7) % 15]);
                #pragma unroll
                for (int i = 0; i < 7; i++)
                    acc = ffma2(kyv[i],
                                fadd2(win[(s + i) % 15], win[(s + 14 - i) % 15]),
                                acc);

                *reinterpret_cast<float2*>(&vbuf[(32 * g + s) * VSTRIDE + 2 * pc]) = acc;
            }
        } else {
            const bool xok = (gxp >= 0) && (gxp + 1 < IMW);
            const int rx0 = refl(gxp);
            const int rx1 = refl(gxp + 1);

            #pragma unroll
            for (int i = 0; i < 14; i++) {
                const int ry = refl(gy0 - 7 + i);
                const float* rp = img + (size_t)ry * IMW;
                if (xok) {
                    win[i] = *reinterpret_cast<const float2*>(rp + gxp);
                } else {
                    win[i].x = rp[rx0]; win[i].y = rp[rx1];
                }
            }
            #pragma unroll
            for (int s = 0; s < 32; s++) {
                const int ry = refl(gy0 + s + 7);
                const float* rp = img + (size_t)ry * IMW;
                float2 nv;
                if (xok) {
                    nv = *reinterpret_cast<const float2*>(rp + gxp);
                } else {
                    nv.x = rp[rx0]; nv.y = rp[rx1];
                }
                win[(14 + s) % 15] = nv;

                float2 acc = fmul2(kyv[7], win[(s + 7) % 15]);
                #pragma unroll
                for (int i = 0; i < 7; i++)
                    acc = ffma2(kyv[i],
                                fadd2(win[(s + i) % 15], win[(s + 14 - i) % 15]),
                                acc);

                *reinterpret_cast<float2*>(&vbuf[(32 * g + s) * VSTRIDE + 2 * pc]) = acc;
            }
        }
    }
    __syncthreads();

    // ---- phase 2: horizontal conv, 8-output runs, FFMA-imm, vbuf -> out ----
    // 14 runs/row * 128 rows = 1792 tasks = exactly 7 per thread.
    // Row-pair interleave keeps each 8-lane LDS.128 phase on 8 distinct
    // 16B banks (addresses {0,16,...,112} mod 128).
    {
        const int X0  = bx * TX;
        const int gyb = by * TY;
        const bool xedge = (bx == NSX - 1);

        #pragma unroll
        for (int it = 0; it < 7; it++) {
            const int t   = it * 256 + tid;
            const int r2  = t / 28;
            const int u   = t - r2 * 28;
            const int row = 2 * r2 + (u & 1);
            const int q   = u >> 1;              // run 0..13

            const float* vp = &vbuf[row * VSTRIDE + q * 8];
            float w[24];
            #pragma unroll
            for (int j = 0; j < 6; j++) {
                const float4 f = *reinterpret_cast<const float4*>(vp + 4 * j);
                w[4 * j]     = f.x;
                w[4 * j + 1] = f.y;
                w[4 * j + 2] = f.z;
                w[4 * j + 3] = f.w;
            }

            // output k (0..7) at tile col q*8+k uses w[1+k .. 15+k]
            float o[8];
            #pragma unroll
            for (int k = 0; k < 8; k++) o[k] = KC[0] * w[1 + k];
            #pragma unroll
            for (int i = 1; i < 15; i++) {
                #pragma unroll
                for (int k = 0; k < 8; k++)
                    o[k] = fmaf(KC[i], w[1 + k + i], o[k]);
            }

            const int gy = gyb + row;
            const int gx = X0 + 8 * q;
            if (!xedge || gx + 7 < IMW) {
                float* op = out + (size_t)gy * IMW + gx;
                *reinterpret_cast<float4*>(op) =
                    make_float4(o[0], o[1], o[2], o[3]);
                *reinterpret_cast<float4*>(op + 4) =
                    make_float4(o[4], o[5], o[6], o[7]);
            }
        }
    }
}

extern "C" void kernel_launch(void* const* d_in, const int* in_sizes, int n_in,
                              void* d_out, int out_size) {
    const float* img = (const float*)d_in[0];
    float* out = (float*)d_out;

    static bool attr_set = false;
    if (!attr_set) {
        cudaFuncSetAttribute(gauss_sep_kernel,
                             cudaFuncAttributeMaxDynamicSharedMemorySize,
                             SMEM_BYTES);
        attr_set = true;
    }

    dim3 grid(NSX, NSY);
    gauss_sep_kernel<<<grid, 256, SMEM_BYTES>>>(img, out);
}

// round 12
// speedup vs baseline: 1.4065x; 1.3702x over previous
#include <cuda_runtime.h>

// 15x15 separable Gaussian, 8192x8192 f32, reflect pad, stride 1.
// Fused separable conv (R5 geometry, verbatim, + interior fast path in phase 1):
//   phase 1: vertical, packed f32x2 symmetric taps, register sliding window,
//            global -> smem vbuf. Interior CTAs (95%) use a bumped row pointer
//            (no refl, no per-row IMAD); border CTAs use the refl path.
//   phase 2: horizontal, 8-output runs, FFMA-imm, row-pair interleaved task
//            map for conflict-free LDS.128 (VSTRIDE=132 -> row stride == 16 mod 128)
// Coefficients hardcoded (problem-fixed Gaussian sigma=3, 15 taps);
// rel_err ~2.4e-7 verified across rounds.

#define IMW 8192
#define IMH 8192
#define TX  112          // output tile width (128 vbuf cols incl. 8+8 halo)
#define TY  80           // output tile height
#define VSTRIDE 132      // floats; 132*4=528 B, 528 % 128 == 16
#define NSX 74           // ceil(8192/112)
#define NSY 103          // ceil(8192/80)

static __device__ __forceinline__ int refl(int i) {
    i = (i < 0) ? -i : i;
    return (i >= IMW) ? (2 * IMW - 2 - i) : i;
}

__device__ __forceinline__ float2 ffma2(float2 a, float2 b, float2 c) {
    unsigned long long ua = *reinterpret_cast<unsigned long long*>(&a);
    unsigned long long ub = *reinterpret_cast<unsigned long long*>(&b);
    unsigned long long uc = *reinterpret_cast<unsigned long long*>(&c);
    unsigned long long ud;
    asm("fma.rn.f32x2 %0, %1, %2, %3;" : "=l"(ud) : "l"(ua), "l"(ub), "l"(uc));
    return *reinterpret_cast<float2*>(&ud);
}

__device__ __forceinline__ float2 fmul2(float2 a, float2 b) {
    unsigned long long ua = *reinterpret_cast<unsigned long long*>(&a);
    unsigned long long ub = *reinterpret_cast<unsigned long long*>(&b);
    unsigned long long ud;
    asm("mul.rn.f32x2 %0, %1, %2;" : "=l"(ud) : "l"(ua), "l"(ub));
    return *reinterpret_cast<float2*>(&ud);
}

__device__ __forceinline__ float2 fadd2(float2 a, float2 b) {
    unsigned long long ua = *reinterpret_cast<unsigned long long*>(&a);
    unsigned long long ub = *reinterpret_cast<unsigned long long*>(&b);
    unsigned long long ud;
    asm("add.rn.f32x2 %0, %1, %2;" : "=l"(ud) : "l"(ua), "l"(ub));
    return *reinterpret_cast<float2*>(&ud);
}

__global__ __launch_bounds__(256, 3)
void gauss_sep_kernel(const float* __restrict__ img,
                      float* __restrict__ out) {
    // normalized 1-D Gaussian, sigma=3, 15 taps (fp32)
    const float KC[15] = {
        0.00884695f, 0.01821590f, 0.03356240f, 0.05533503f,
        0.08163801f, 0.10777792f, 0.12732457f, 0.13459834f,
        0.12732457f, 0.10777792f, 0.08163801f, 0.05533503f,
        0.03356240f, 0.01821590f, 0.00884695f };

    __shared__ __align__(16) float vbuf[TY * VSTRIDE];   // 42.24 KB

    const int tid = threadIdx.x;
    const int bx = blockIdx.x;
    const int by = blockIdx.y;

    // ---- phase 1: vertical conv (packed f32x2, symmetric), global -> vbuf ----
    {
        const int pc = tid & 63;        // float2 column 0..63 (128 vbuf cols)
        const int g  = tid >> 6;        // y-group 0..3 (20 vbuf rows each)
        const int gxp = bx * TX - 8 + 2 * pc;          // global col of pair
        const int gy0 = by * TY + 20 * g;              // first output row of group

        float2 kyv[8];
        #pragma unroll
        for (int i = 0; i < 8; i++) kyv[i] = make_float2(KC[i], KC[i]);

        float2 win[15];

        const bool interior = (bx > 0) && (bx < NSX - 1) && (by > 0) && (by < NSY - 1);

        if (interior) {
            // fast path: no reflection anywhere; bumped row pointer
            const float* rp = img + (size_t)(gy0 - 7) * IMW + gxp;
            #pragma unroll
            for (int i = 0; i < 14; i++) {
                win[i] = *reinterpret_cast<const float2*>(rp);
                rp += IMW;
            }
            #pragma unroll
            for (int s = 0; s < 20; s++) {
                const float2 nv = *reinterpret_cast<const float2*>(rp);
                rp += IMW;
                win[(14 + s) % 15] = nv;

                float2 acc = fmul2(kyv[7], win[(s + 7) % 15]);
                #pragma unroll
                for (int i = 0; i < 7; i++)
                    acc = ffma2(kyv[i],
                                fadd2(win[(s + i) % 15], win[(s + 14 - i) % 15]),
                                acc);

                *reinterpret_cast<float2*>(&vbuf[(20 * g + s) * VSTRIDE + 2 * pc]) = acc;
            }
        } else {
            const bool xok = (gxp >= 0) && (gxp + 1 < IMW);
            const int rx0 = refl(gxp);
            const int rx1 = refl(gxp + 1);

            #pragma unroll
            for (int i = 0; i < 14; i++) {
                const int ry = refl(gy0 - 7 + i);
                const float* rp = img + (size_t)ry * IMW;
                if (xok) {
                    win[i] = *reinterpret_cast<const float2*>(rp + gxp);
                } else {
                    win[i].x = rp[rx0]; win[i].y = rp[rx1];
                }
            }
            #pragma unroll
            for (int s = 0; s < 20; s++) {
                const int ry = refl(gy0 + s + 7);
                const float* rp = img + (size_t)ry * IMW;
                float2 nv;
                if (xok) {
                    nv = *reinterpret_cast<const float2*>(rp + gxp);
                } else {
                    nv.x = rp[rx0]; nv.y = rp[rx1];
                }
                win[(14 + s) % 15] = nv;

                float2 acc = fmul2(kyv[7], win[(s + 7) % 15]);
                #pragma unroll
                for (int i = 0; i < 7; i++)
                    acc = ffma2(kyv[i],
                                fadd2(win[(s + i) % 15], win[(s + 14 - i) % 15]),
                                acc);

                *reinterpret_cast<float2*>(&vbuf[(20 * g + s) * VSTRIDE + 2 * pc]) = acc;
            }
        }
    }
    __syncthreads();

    // ---- phase 2: horizontal conv, 8-output runs, FFMA-imm, vbuf -> out ----
    // 14 runs/row * 80 rows = 1120 tasks. Row-pair interleave keeps each
    // 8-lane LDS.128 phase on 8 distinct 16B banks (conflict-free).
    {
        const int X0  = bx * TX;
        const int gyb = by * TY;

        for (int t = tid; t < 1120; t += 256) {
            const int r2  = t / 28;
            const int u   = t - r2 * 28;
            const int row = 2 * r2 + (u & 1);
            const int q   = u >> 1;              // run 0..13

            const float* vp = &vbuf[row * VSTRIDE + q * 8];
            float w[24];
            #pragma unroll
            for (int j = 0; j < 6; j++) {
                const float4 f = *reinterpret_cast<const float4*>(vp + 4 * j);
                w[4 * j]     = f.x;
                w[4 * j + 1] = f.y;
                w[4 * j + 2] = f.z;
                w[4 * j + 3] = f.w;
            }

            // output k (0..7) at tile col q*8+k uses w[1+k .. 15+k]
            float o[8];
            #pragma unroll
            for (int k = 0; k < 8; k++) o[k] = KC[0] * w[1 + k];
            #pragma unroll
            for (int i = 1; i < 15; i++) {
                #pragma unroll
                for (int k = 0; k < 8; k++)
                    o[k] = fmaf(KC[i], w[1 + k + i], o[k]);
            }

            const int gy = gyb + row;
            const int gx = X0 + 8 * q;
            if (gy < IMH && gx + 7 < IMW) {
                float* op = out + (size_t)gy * IMW + gx;
                *reinterpret_cast<float4*>(op) =
                    make_float4(o[0], o[1], o[2], o[3]);
                *reinterpret_cast<float4*>(op + 4) =
                    make_float4(o[4], o[5], o[6], o[7]);
            }
        }
    }
}

extern "C" void kernel_launch(void* const* d_in, const int* in_sizes, int n_in,
                              void* d_out, int out_size) {
    const float* img = (const float*)d_in[0];
    float* out = (float*)d_out;

    dim3 grid(NSX, NSY);
    gauss_sep_kernel<<<grid, 256>>>(img, out);
}